// round 1
// baseline (speedup 1.0000x reference)
#include <cuda_runtime.h>
#include <math.h>

// Problem constants
#define BGRAPH   256
#define M_ATOMS  48
#define NNODES   (BGRAPH * M_ATOMS)          // 12288
#define GRAPH_E  (M_ATOMS * (M_ATOMS - 1))   // 2256
#define EDGES    (BGRAPH * GRAPH_E)          // 577536
#define KRBF     32
#define NSH      25
#define FEAT     (KRBF + NSH)                // 57
#define HS       128
#define CUTOFF_INV (1.0f / 15.0f)

// Output layout (floats), concatenated in reference return order:
// feat [E,57] | node_emb [N,128] | edge_index [2,E] | transpose_index [E]
#define FEAT_OFF 0
#define EMB_OFF  ((size_t)EDGES * FEAT)                 // 32,919,552
#define EI_OFF   (EMB_OFF + (size_t)NNODES * HS)        // 34,492,416
#define TR_OFF   (EI_OFF + 2 * (size_t)EDGES)           // 35,647,488

// ---------------------------------------------------------------------------
// Edge kernel: 1 thread = 1 edge. Computes RBF(32) + SH(25) into a per-warp
// smem tile [32][57] (stride 57 odd -> bank-conflict-free), then streams the
// tile out coalesced. Also writes edge_index / transpose_index (coalesced).
// ---------------------------------------------------------------------------
__global__ void __launch_bounds__(128) edge_feat_kernel(
    const float* __restrict__ pos,
    const float* __restrict__ alpha,
    float* __restrict__ out)
{
    __shared__ float tile[4][32 * FEAT];

    const int e    = blockIdx.x * 128 + threadIdx.x;   // grid sized exactly
    const int lane = threadIdx.x & 31;
    const int w    = threadIdx.x >> 5;

    // ---- index math (constant divisors -> mulhi sequences) ----
    const int g = e / GRAPH_E;
    const int t = e - g * GRAPH_E;
    const int s = t / (M_ATOMS - 1);
    const int k = t - s * (M_ATOMS - 1);
    const int d = k + (k >= s);
    const int src = g * M_ATOMS + s;
    const int dst = g * M_ATOMS + d;
    const int tr  = g * GRAPH_E + d * (M_ATOMS - 1) + s - (d < s);

    // ---- geometry ----
    const float ex = pos[dst * 3 + 0] - pos[src * 3 + 0];
    const float ey = pos[dst * 3 + 1] - pos[src * 3 + 1];
    const float ez = pos[dst * 3 + 2] - pos[src * 3 + 2];
    const float r2 = ex * ex + ey * ey + ez * ez;
    float r = sqrtf(r2);
    r = fmaxf(r, 1e-6f);
    const float rinv = 1.0f / r;
    const float x = ex * rinv, y = ey * rinv, z = ez * rinv;

    float* row = &tile[w][lane * FEAT];

    // ---- cutoff ----
    const float rc  = r * CUTOFF_INV;
    const float den = fmaxf((1.0f - rc) * (1.0f + rc), 1e-9f);
    const float fcut = (rc < 1.0f) ? expf(-(rc * rc) / den) : 0.0f;

    // ---- exponential Bernstein RBF via two-sided ratio recurrence ----
    // t_v = C(31,v) * p^(31-v) * q^v,  p = exp(xx), q = -expm1(xx)
    const float aeff = 0.5f * alpha[0];
    const float xx = -aeff * r;
    const float q = -expm1f(xx);
    const float p = 1.0f - q;

    // upward half: v = 0..15, start at p^31 (underflow here is provably harmless)
    {
        const float p2 = p * p, p4 = p2 * p2, p8 = p4 * p4, p16 = p8 * p8;
        float tv = p16 * p8 * p4 * p2 * p;        // p^31
        const float qop = q / p;
        row[0] = fcut * tv;
#pragma unroll
        for (int v = 0; v < 15; ++v) {
            tv *= qop * ((float)(31 - v) / (float)(v + 1));
            row[v + 1] = fcut * tv;
        }
    }
    // downward half: v = 31..16, start at q^31
    {
        const float q2 = q * q, q4 = q2 * q2, q8 = q4 * q4, q16 = q8 * q8;
        float u = q16 * q8 * q4 * q2 * q;         // q^31
        const float poq = p / q;
        row[31] = fcut * u;
#pragma unroll
        for (int v = 31; v > 16; --v) {
            u *= poq * ((float)v / (float)(32 - v));
            row[v - 1] = fcut * u;
        }
    }

    // ---- real spherical harmonics, component-normalized, l <= 4 ----
    // C_m + i S_m = (x + i y)^m ; Q via Legendre recurrence (no Condon-Shortley)
    const float C2 = x * x - y * y,      S2 = 2.0f * x * y;
    const float C3 = C2 * x - S2 * y,    S3 = S2 * x + C2 * y;
    const float C4 = C3 * x - S3 * y,    S4 = S3 * x + C3 * y;
    const float z2 = z * z;

    const float q20 = 1.5f  * z2 - 0.5f;           // Q_2^0
    const float q30 = (2.5f * z2 - 1.5f) * z;      // Q_3^0
    const float q40 = (4.375f * z2 - 3.75f) * z2 + 0.375f; // Q_4^0
    const float q31 = 7.5f  * z2 - 1.5f;           // Q_3^1
    const float q41 = (17.5f * z2 - 7.5f) * z;     // Q_4^1
    const float q42 = 52.5f * z2 - 7.5f;           // Q_4^2

    float* sh = row + KRBF;
    sh[0]  = 1.0f;
    sh[1]  = 1.7320508f * y;
    sh[2]  = 1.7320508f * z;
    sh[3]  = 1.7320508f * x;
    sh[4]  = 1.9364917f * S2;
    sh[5]  = 3.8729833f * y * z;
    sh[6]  = 2.2360680f * q20;
    sh[7]  = 3.8729833f * x * z;
    sh[8]  = 1.9364917f * C2;
    sh[9]  = 2.0916500f * S3;
    sh[10] = 5.1234756f * z * S2;
    sh[11] = 1.0801234f * q31 * y;
    sh[12] = 2.6457513f * q30;
    sh[13] = 1.0801234f * q31 * x;
    sh[14] = 5.1234756f * z * C2;
    sh[15] = 2.0916500f * C3;
    sh[16] = 2.2185299f * S4;
    sh[17] = 6.2749501f * z * S3;
    sh[18] = 0.2236068f * q42 * S2;
    sh[19] = 0.9486833f * q41 * y;
    sh[20] = 3.0f       * q40;
    sh[21] = 0.9486833f * q41 * x;
    sh[22] = 0.2236068f * q42 * C2;
    sh[23] = 6.2749501f * z * S3 * 0.0f + 6.2749501f * z * C3; // (see below)
    sh[24] = 2.2185299f * C4;
    // fix idx23 cleanly (m=+3 uses C3):
    sh[23] = 6.2749501f * z * C3;

    // ---- index outputs (already coalesced: consecutive e -> consecutive addr)
    out[EI_OFF + e]         = (float)dst;
    out[EI_OFF + EDGES + e] = (float)src;
    out[TR_OFF + e]         = (float)tr;

    // ---- stream the warp's 32x57 feat tile out, fully coalesced ----
    __syncwarp();
    const float* sp = tile[w];
    float* op = out + (size_t)(blockIdx.x * 128 + w * 32) * FEAT;
#pragma unroll 8
    for (int i = lane; i < 32 * FEAT; i += 32)
        op[i] = sp[i];
}

// ---------------------------------------------------------------------------
// Node embedding gather: warp n copies row embed_table[an[n]] (128 floats) as
// 32 float4s. Table (10 KB) is L1/L2 resident.
// ---------------------------------------------------------------------------
__global__ void __launch_bounds__(256) emb_kernel(
    const int* __restrict__ an,
    const float4* __restrict__ table4,
    float4* __restrict__ out4)
{
    const int i = blockIdx.x * 256 + threadIdx.x;  // i < NNODES*32 exactly
    const int n = i >> 5;
    const int c = i & 31;
    out4[i] = table4[an[n] * 32 + c];
}

extern "C" void kernel_launch(void* const* d_in, const int* in_sizes, int n_in,
                              void* d_out, int out_size)
{
    const float* pos   = (const float*)d_in[0];
    const int*   an    = (const int*)d_in[1];
    const float* table = (const float*)d_in[2];
    const float* alpha = (const float*)d_in[3];
    float* out = (float*)d_out;

    // EDGES = 577536 = 4512 * 128 exactly
    edge_feat_kernel<<<EDGES / 128, 128>>>(pos, alpha, out);
    // NNODES*32 = 393216 = 1536 * 256 exactly
    emb_kernel<<<(NNODES * 32) / 256, 256>>>(an, (const float4*)table,
                                             (float4*)(out + EMB_OFF));
}

// round 3
// speedup vs baseline: 1.0549x; 1.0549x over previous
#include <cuda_runtime.h>
#include <math.h>

// Problem constants
#define BGRAPH   256
#define M_ATOMS  48
#define NNODES   (BGRAPH * M_ATOMS)          // 12288
#define GRAPH_E  (M_ATOMS * (M_ATOMS - 1))   // 2256
#define EDGES    (BGRAPH * GRAPH_E)          // 577536
#define KRBF     32
#define NSH      25
#define FEAT     (KRBF + NSH)                // 57
#define HS       128
#define CUTOFF_INV (1.0f / 15.0f)

// Output layout (floats), concatenated in reference return order:
// feat [E,57] | node_emb [N,128] | edge_index [2,E] | transpose_index [E]
#define EMB_OFF  ((size_t)EDGES * FEAT)                 // 32,919,552
#define EI_OFF   (EMB_OFF + (size_t)NNODES * HS)        // 34,492,416
#define TR_OFF   (EI_OFF + 2 * (size_t)EDGES)           // 35,647,488

#define EDGE_BLOCKS (EDGES / 128)                        // 4512
#define EMB_BLOCKS  ((NNODES * 32) / 128)                // 3072 (float4 units)
#define TOTAL_BLOCKS (EDGE_BLOCKS + EMB_BLOCKS)          // 7584

// ---------------------------------------------------------------------------
// Fused kernel.
//  blocks [0, 4512): 1 thread = 1 edge. RBF(32)+SH(25) into per-warp smem tile
//    [32][57] (odd stride -> conflict-free), streamed out as STG.128.
//  blocks [4512, 7584): embedding gather, 1 thread = 1 float4 of node_emb.
// ---------------------------------------------------------------------------
__global__ void __launch_bounds__(128) fused_kernel(
    const float*  __restrict__ pos,
    const int*    __restrict__ an,
    const float4* __restrict__ table4,
    const float*  __restrict__ alpha,
    float* __restrict__ out)
{
    __shared__ __align__(16) float tile[4][32 * FEAT];

    if (blockIdx.x >= EDGE_BLOCKS) {
        // ---------------- embedding gather ----------------
        const int i = (blockIdx.x - EDGE_BLOCKS) * 128 + threadIdx.x; // < NNODES*32
        const int n = i >> 5;
        const int c = i & 31;
        float4* out4 = (float4*)(out + EMB_OFF);
        out4[i] = table4[an[n] * 32 + c];
        return;
    }

    const int e    = blockIdx.x * 128 + threadIdx.x;   // grid sized exactly
    const int lane = threadIdx.x & 31;
    const int w    = threadIdx.x >> 5;

    // ---- index math (constant divisors -> mulhi sequences) ----
    const int g = e / GRAPH_E;
    const int t = e - g * GRAPH_E;
    const int s = t / (M_ATOMS - 1);
    const int k = t - s * (M_ATOMS - 1);
    const int d = k + (k >= s);
    const int src = g * M_ATOMS + s;
    const int dst = g * M_ATOMS + d;
    const int tr  = g * GRAPH_E + d * (M_ATOMS - 1) + s - (d < s);

    // ---- geometry ----
    const float ex = pos[dst * 3 + 0] - pos[src * 3 + 0];
    const float ey = pos[dst * 3 + 1] - pos[src * 3 + 1];
    const float ez = pos[dst * 3 + 2] - pos[src * 3 + 2];
    const float r2 = ex * ex + ey * ey + ez * ez;
    float r = sqrtf(r2);
    r = fmaxf(r, 1e-6f);
    const float rinv = 1.0f / r;
    const float x = ex * rinv, y = ey * rinv, z = ez * rinv;

    float* row = &tile[w][lane * FEAT];

    // ---- cutoff ----
    const float rc  = r * CUTOFF_INV;
    const float den = fmaxf((1.0f - rc) * (1.0f + rc), 1e-9f);
    const float fcut = (rc < 1.0f) ? expf(-(rc * rc) / den) : 0.0f;

    // ---- exponential Bernstein RBF via two-sided ratio recurrence ----
    // t_v = C(31,v) * p^(31-v) * q^v,  p = exp(xx), q = -expm1(xx)
    const float aeff = 0.5f * alpha[0];
    const float xx = -aeff * r;
    const float q = -expm1f(xx);
    const float p = 1.0f - q;

    // upward half: v = 0..15, start at p^31 (underflow here is provably harmless)
    {
        const float p2 = p * p, p4 = p2 * p2, p8 = p4 * p4, p16 = p8 * p8;
        float tv = p16 * p8 * p4 * p2 * p;        // p^31
        const float qop = q / p;
        row[0] = fcut * tv;
#pragma unroll
        for (int v = 0; v < 15; ++v) {
            tv *= qop * ((float)(31 - v) / (float)(v + 1));
            row[v + 1] = fcut * tv;
        }
    }
    // downward half: v = 31..16, start at q^31
    {
        const float q2 = q * q, q4 = q2 * q2, q8 = q4 * q4, q16 = q8 * q8;
        float u = q16 * q8 * q4 * q2 * q;         // q^31
        const float poq = p / q;
        row[31] = fcut * u;
#pragma unroll
        for (int v = 31; v > 16; --v) {
            u *= poq * ((float)v / (float)(32 - v));
            row[v - 1] = fcut * u;
        }
    }

    // ---- real spherical harmonics, component-normalized, l <= 4 ----
    const float C2 = x * x - y * y,      S2 = 2.0f * x * y;
    const float C3 = C2 * x - S2 * y,    S3 = S2 * x + C2 * y;
    const float C4 = C3 * x - S3 * y,    S4 = S3 * x + C3 * y;
    const float z2 = z * z;

    const float q20 = 1.5f  * z2 - 0.5f;                    // Q_2^0
    const float q30 = (2.5f * z2 - 1.5f) * z;               // Q_3^0
    const float q40 = (4.375f * z2 - 3.75f) * z2 + 0.375f;  // Q_4^0
    const float q31 = 7.5f  * z2 - 1.5f;                    // Q_3^1
    const float q41 = (17.5f * z2 - 7.5f) * z;              // Q_4^1
    const float q42 = 52.5f * z2 - 7.5f;                    // Q_4^2

    float* sh = row + KRBF;
    sh[0]  = 1.0f;
    sh[1]  = 1.7320508f * y;
    sh[2]  = 1.7320508f * z;
    sh[3]  = 1.7320508f * x;
    sh[4]  = 1.9364917f * S2;
    sh[5]  = 3.8729833f * y * z;
    sh[6]  = 2.2360680f * q20;
    sh[7]  = 3.8729833f * x * z;
    sh[8]  = 1.9364917f * C2;
    sh[9]  = 2.0916500f * S3;
    sh[10] = 5.1234756f * z * S2;
    sh[11] = 1.0801234f * q31 * y;
    sh[12] = 2.6457513f * q30;
    sh[13] = 1.0801234f * q31 * x;
    sh[14] = 5.1234756f * z * C2;
    sh[15] = 2.0916500f * C3;
    sh[16] = 2.2185299f * S4;
    sh[17] = 6.2749501f * z * S3;
    sh[18] = 0.2236068f * q42 * S2;
    sh[19] = 0.9486833f * q41 * y;
    sh[20] = 3.0f       * q40;
    sh[21] = 0.9486833f * q41 * x;
    sh[22] = 0.2236068f * q42 * C2;
    sh[23] = 6.2749501f * z * C3;
    sh[24] = 2.2185299f * C4;

    // ---- index outputs (coalesced) ----
    out[EI_OFF + e]         = (float)dst;
    out[EI_OFF + EDGES + e] = (float)src;
    out[TR_OFF + e]         = (float)tr;

    // ---- stream the warp's 32x57 feat tile out as float4 (STG.128) ----
    // tile = 1824 floats = 456 float4; warp base = e_base*57*4 B = mult of 7296 B
    __syncwarp();
    const float4* sp4 = (const float4*)tile[w];
    float4* op4 = (float4*)(out + (size_t)(blockIdx.x * 128 + w * 32) * FEAT);
#pragma unroll
    for (int i = lane; i < (32 * FEAT) / 4; i += 32)
        op4[i] = sp4[i];
}

extern "C" void kernel_launch(void* const* d_in, const int* in_sizes, int n_in,
                              void* d_out, int out_size)
{
    const float* pos   = (const float*)d_in[0];
    const int*   an    = (const int*)d_in[1];
    const float* table = (const float*)d_in[2];
    const float* alpha = (const float*)d_in[3];
    float* out = (float*)d_out;

    fused_kernel<<<TOTAL_BLOCKS, 128>>>(pos, an, (const float4*)table, alpha, out);
}